// round 4
// baseline (speedup 1.0000x reference)
#include <cuda_runtime.h>
#include <math.h>

// ---------------------------------------------------------------------------
// CrystalGraphAttention  (B=8, N=1024, D=256, H=8, dk=dv=64)
//
//   q,k,v = X @ W{q,k,v}         -> [B,H,N,64]   (kernel 1, fp32 SIMT)
//   flash attention, tf32 tensor-core 3-pass (hi/lo split)   (kernel 2)
//   out = ctx @ Wo + bo          -> [B,N,256]    (kernel 3, fp32 SIMT)
// ---------------------------------------------------------------------------

#define NEGBIG (-1.0e9f)

static __device__ float g_q [8 * 8 * 1024 * 64];    // [B,H,N,64]
static __device__ float g_k [8 * 8 * 1024 * 64];
static __device__ float g_v [8 * 8 * 1024 * 64];
static __device__ float g_ctx[8 * 1024 * 512];      // [B*N, H*64]

// ---------------------------------------------------------------------------
// Kernel 1: fused QKV projection (unchanged from R3).
// ---------------------------------------------------------------------------
__global__ __launch_bounds__(256) void qkv_kernel(
    const float* __restrict__ X,
    const float* __restrict__ Wq,
    const float* __restrict__ Wk,
    const float* __restrict__ Wv)
{
    __shared__ float As[128 * 33];
    __shared__ float Bs[32 * 68];

    const int tid = threadIdx.x;
    const int mt = blockIdx.x;
    const int h  = blockIdx.y;
    const int w  = blockIdx.z;
    const float* W = (w == 0) ? Wq : (w == 1) ? Wk : Wv;
    float* Out     = (w == 0) ? g_q : (w == 1) ? g_k : g_v;

    const int tm = tid >> 4, tn = tid & 15;
    const int lr = tid >> 3, lc = tid & 7;
    const int br = tid >> 4, bc = tid & 15;

    float acc[8][4];
    #pragma unroll
    for (int i = 0; i < 8; i++)
        #pragma unroll
        for (int j = 0; j < 4; j++) acc[i][j] = 0.f;

    for (int k0 = 0; k0 < 256; k0 += 32) {
        #pragma unroll
        for (int t = 0; t < 4; t++) {
            int m = lr + 32 * t;
            float4 xv = *(const float4*)&X[(size_t)(mt * 128 + m) * 256 + k0 + lc * 4];
            As[m * 33 + lc * 4 + 0] = xv.x;
            As[m * 33 + lc * 4 + 1] = xv.y;
            As[m * 33 + lc * 4 + 2] = xv.z;
            As[m * 33 + lc * 4 + 3] = xv.w;
        }
        #pragma unroll
        for (int t = 0; t < 2; t++) {
            int k = br + 16 * t;
            float4 wv = *(const float4*)&W[(size_t)(k0 + k) * 512 + h * 64 + bc * 4];
            *(float4*)&Bs[k * 68 + bc * 4] = wv;
        }
        __syncthreads();

        #pragma unroll 8
        for (int kk = 0; kk < 32; kk++) {
            float a[8];
            #pragma unroll
            for (int i = 0; i < 8; i++) a[i] = As[(tm * 8 + i) * 33 + kk];
            float4 bv = *(const float4*)&Bs[kk * 68 + tn * 4];
            #pragma unroll
            for (int i = 0; i < 8; i++) {
                acc[i][0] += a[i] * bv.x;
                acc[i][1] += a[i] * bv.y;
                acc[i][2] += a[i] * bv.z;
                acc[i][3] += a[i] * bv.w;
            }
        }
        __syncthreads();
    }

    #pragma unroll
    for (int i = 0; i < 8; i++) {
        int m = mt * 128 + tm * 8 + i;
        int b = m >> 10, s = m & 1023;
        float4 r;
        r.x = acc[i][0]; r.y = acc[i][1]; r.z = acc[i][2]; r.w = acc[i][3];
        *(float4*)&Out[(size_t)((b * 8 + h) * 1024 + s) * 64 + tn * 4] = r;
    }
}

// ---------------------------------------------------------------------------
// tf32 mma helpers
// ---------------------------------------------------------------------------
#define MMA_TF32(c, a, b0, b1)                                              \
    asm volatile(                                                           \
        "mma.sync.aligned.m16n8k8.row.col.f32.tf32.tf32.f32 "               \
        "{%0,%1,%2,%3}, {%4,%5,%6,%7}, {%8,%9}, {%0,%1,%2,%3};"             \
        : "+f"((c)[0]), "+f"((c)[1]), "+f"((c)[2]), "+f"((c)[3])            \
        : "r"((a)[0]), "r"((a)[1]), "r"((a)[2]), "r"((a)[3]),               \
          "r"(b0), "r"(b1))

__device__ __forceinline__ void split_tf32(float x, unsigned& hi, unsigned& lo)
{
    unsigned h = __float_as_uint(x) & 0xFFFFE000u;   // keep 10 mantissa bits
    hi = h;
    lo = __float_as_uint(x - __uint_as_float(h));    // exact residual
}

// ---------------------------------------------------------------------------
// Kernel 2: flash attention, tensor-core tf32 3-pass.
// grid = (8 qtiles, 8 heads, 8 batches), block = 256 (8 warps).
// Q-tile = 128 rows (16/warp, register-resident hi/lo fragments).
// K-tile = 64 keys; K,V staged in smem with stride-68 padding (conflict-free).
// Fragment maps (m16n8k8 tf32, g = lane>>2, tg = lane&3):
//   A: a0=(g,tg) a1=(g+8,tg) a2=(g,tg+4) a3=(g+8,tg+4)
//   B: b0=(k=tg, n=g) b1=(k=tg+4, n=g)
//   C: c0=(g,2tg) c1=(g,2tg+1) c2=(g+8,2tg) c3=(g+8,2tg+1)
// ---------------------------------------------------------------------------
__global__ __launch_bounds__(256, 1) void attn_kernel(
    const float* __restrict__ em,     // [B,1,N,N]
    const float* __restrict__ dw)     // [B,N]
{
    __shared__ float Ks[64 * 68];     // [key][d]
    __shared__ float Vs[64 * 68];     // [key][d]

    const int tid  = threadIdx.x;
    const int wid  = tid >> 5;
    const int lane = tid & 31;
    const int g    = lane >> 2;
    const int tg   = lane & 3;
    const int qt = blockIdx.x, h = blockIdx.y, b = blockIdx.z;
    const int qrow0 = qt * 128 + wid * 16;

    const float* qb = &g_q[(size_t)((b * 8 + h) * 1024 + qrow0) * 64];
    const float* kb = &g_k[(size_t)(b * 8 + h) * 1024 * 64];
    const float* vb = &g_v[(size_t)(b * 8 + h) * 1024 * 64];
    const float* emb = em + (size_t)b * 1024 * 1024;
    const float* dwb = dw + b * 1024;

    // ---- Q fragments, hi/lo split, register-resident for whole kernel ----
    unsigned qhi[8][4], qlo[8][4];
    #pragma unroll
    for (int kc = 0; kc < 8; kc++) {
        float a0 = qb[(size_t)g * 64        + kc * 8 + tg];
        float a1 = qb[(size_t)(g + 8) * 64  + kc * 8 + tg];
        float a2 = qb[(size_t)g * 64        + kc * 8 + tg + 4];
        float a3 = qb[(size_t)(g + 8) * 64  + kc * 8 + tg + 4];
        split_tf32(a0, qhi[kc][0], qlo[kc][0]);
        split_tf32(a1, qhi[kc][1], qlo[kc][1]);
        split_tf32(a2, qhi[kc][2], qlo[kc][2]);
        split_tf32(a3, qhi[kc][3], qlo[kc][3]);
    }

    float O[8][4];
    #pragma unroll
    for (int nt = 0; nt < 8; nt++)
        #pragma unroll
        for (int j = 0; j < 4; j++) O[nt][j] = 0.f;
    float mi0 = -1e30f, mi1 = -1e30f, li0 = 0.f, li1 = 0.f;

    for (int kt = 0; kt < 16; kt++) {
        __syncthreads();
        // ---- stage K,V tiles (64x64, stride 68) ----
        {
            int r = tid >> 4, c = (tid & 15) * 4;
            #pragma unroll
            for (int t = 0; t < 4; t++, r += 16) {
                *(float4*)&Ks[r * 68 + c] =
                    *(const float4*)&kb[(size_t)(kt * 64 + r) * 64 + c];
                *(float4*)&Vs[r * 68 + c] =
                    *(const float4*)&vb[(size_t)(kt * 64 + r) * 64 + c];
            }
        }

        // ---- prefetch mask + distance weights for this tile ----
        float2 mk0[8], mk1[8], dv2[8];
        {
            const float* er0 = emb + (size_t)(qrow0 + g) * 1024 + kt * 64;
            const float* er1 = er0 + (size_t)8 * 1024;
            const float* dr  = dwb + kt * 64;
            #pragma unroll
            for (int nt = 0; nt < 8; nt++) {
                mk0[nt] = *(const float2*)&er0[nt * 8 + 2 * tg];
                mk1[nt] = *(const float2*)&er1[nt * 8 + 2 * tg];
                dv2[nt] = *(const float2*)&dr [nt * 8 + 2 * tg];
            }
        }
        __syncthreads();

        // ---- S = Q K^T  (3-pass tf32) ----
        float S[8][4];
        #pragma unroll
        for (int nt = 0; nt < 8; nt++) {
            S[nt][0] = S[nt][1] = S[nt][2] = S[nt][3] = 0.f;
            #pragma unroll
            for (int kc = 0; kc < 8; kc++) {
                float x0 = Ks[(nt * 8 + g) * 68 + kc * 8 + tg];
                float x1 = Ks[(nt * 8 + g) * 68 + kc * 8 + tg + 4];
                unsigned b0h, b0l, b1h, b1l;
                split_tf32(x0, b0h, b0l);
                split_tf32(x1, b1h, b1l);
                MMA_TF32(S[nt], qhi[kc], b0h, b1h);
                MMA_TF32(S[nt], qhi[kc], b0l, b1l);
                MMA_TF32(S[nt], qlo[kc], b0h, b1h);
            }
        }

        // ---- mask + distance modulation + online softmax ----
        float rm0 = -1e30f, rm1 = -1e30f;
        #pragma unroll
        for (int nt = 0; nt < 8; nt++) {
            float l0 = (S[nt][0] * 0.125f + (1.f - mk0[nt].x) * NEGBIG) * dv2[nt].x;
            float l1 = (S[nt][1] * 0.125f + (1.f - mk0[nt].y) * NEGBIG) * dv2[nt].y;
            float l2 = (S[nt][2] * 0.125f + (1.f - mk1[nt].x) * NEGBIG) * dv2[nt].x;
            float l3 = (S[nt][3] * 0.125f + (1.f - mk1[nt].y) * NEGBIG) * dv2[nt].y;
            S[nt][0] = l0; S[nt][1] = l1; S[nt][2] = l2; S[nt][3] = l3;
            rm0 = fmaxf(rm0, fmaxf(l0, l1));
            rm1 = fmaxf(rm1, fmaxf(l2, l3));
        }
        #pragma unroll
        for (int off = 1; off <= 2; off <<= 1) {
            rm0 = fmaxf(rm0, __shfl_xor_sync(0xffffffffu, rm0, off));
            rm1 = fmaxf(rm1, __shfl_xor_sync(0xffffffffu, rm1, off));
        }
        float nm0 = fmaxf(mi0, rm0), nm1 = fmaxf(mi1, rm1);
        float corr0 = __expf(mi0 - nm0), corr1 = __expf(mi1 - nm1);

        float rs0 = 0.f, rs1 = 0.f;
        #pragma unroll
        for (int nt = 0; nt < 8; nt++) {
            float p0 = __expf(S[nt][0] - nm0);
            float p1 = __expf(S[nt][1] - nm0);
            float p2 = __expf(S[nt][2] - nm1);
            float p3 = __expf(S[nt][3] - nm1);
            S[nt][0] = p0; S[nt][1] = p1; S[nt][2] = p2; S[nt][3] = p3;
            rs0 += p0 + p1; rs1 += p2 + p3;
        }
        #pragma unroll
        for (int off = 1; off <= 2; off <<= 1) {
            rs0 += __shfl_xor_sync(0xffffffffu, rs0, off);
            rs1 += __shfl_xor_sync(0xffffffffu, rs1, off);
        }
        li0 = li0 * corr0 + rs0;  mi0 = nm0;
        li1 = li1 * corr1 + rs1;  mi1 = nm1;
        #pragma unroll
        for (int nt = 0; nt < 8; nt++) {
            O[nt][0] *= corr0; O[nt][1] *= corr0;
            O[nt][2] *= corr1; O[nt][3] *= corr1;
        }

        // ---- repack P: C-fragment -> A-fragment via shuffles ----
        unsigned phi[8][4], plo[8][4];
        {
            int src0 = (lane & ~3) | (tg >> 1);
            int src1 = src0 + 2;
            #pragma unroll
            for (int kc = 0; kc < 8; kc++) {
                float v00 = __shfl_sync(0xffffffffu, S[kc][0], src0);
                float v01 = __shfl_sync(0xffffffffu, S[kc][1], src0);
                float v02 = __shfl_sync(0xffffffffu, S[kc][2], src0);
                float v03 = __shfl_sync(0xffffffffu, S[kc][3], src0);
                float v10 = __shfl_sync(0xffffffffu, S[kc][0], src1);
                float v11 = __shfl_sync(0xffffffffu, S[kc][1], src1);
                float v12 = __shfl_sync(0xffffffffu, S[kc][2], src1);
                float v13 = __shfl_sync(0xffffffffu, S[kc][3], src1);
                float a0 = (tg & 1) ? v01 : v00;   // (g,    tg)
                float a1 = (tg & 1) ? v03 : v02;   // (g+8,  tg)
                float a2 = (tg & 1) ? v11 : v10;   // (g,    tg+4)
                float a3 = (tg & 1) ? v13 : v12;   // (g+8,  tg+4)
                split_tf32(a0, phi[kc][0], plo[kc][0]);
                split_tf32(a1, phi[kc][1], plo[kc][1]);
                split_tf32(a2, phi[kc][2], plo[kc][2]);
                split_tf32(a3, phi[kc][3], plo[kc][3]);
            }
        }

        // ---- O += P V  (3-pass tf32) ----
        #pragma unroll
        for (int nt = 0; nt < 8; nt++) {
            #pragma unroll
            for (int kc = 0; kc < 8; kc++) {
                float x0 = Vs[(kc * 8 + tg) * 68     + nt * 8 + g];
                float x1 = Vs[(kc * 8 + tg + 4) * 68 + nt * 8 + g];
                unsigned b0h, b0l, b1h, b1l;
                split_tf32(x0, b0h, b0l);
                split_tf32(x1, b1h, b1l);
                MMA_TF32(O[nt], phi[kc], b0h, b1h);
                MMA_TF32(O[nt], phi[kc], b0l, b1l);
                MMA_TF32(O[nt], plo[kc], b0h, b1h);
            }
        }
    }

    // ---- epilogue: normalize and write ctx ----
    float inv0 = 1.f / li0, inv1 = 1.f / li1;
    #pragma unroll
    for (int nt = 0; nt < 8; nt++) {
        float2 r0, r1;
        r0.x = O[nt][0] * inv0; r0.y = O[nt][1] * inv0;
        r1.x = O[nt][2] * inv1; r1.y = O[nt][3] * inv1;
        *(float2*)&g_ctx[(size_t)(b * 1024 + qrow0 + g) * 512
                         + h * 64 + nt * 8 + 2 * tg] = r0;
        *(float2*)&g_ctx[(size_t)(b * 1024 + qrow0 + g + 8) * 512
                         + h * 64 + nt * 8 + 2 * tg] = r1;
    }
}

// ---------------------------------------------------------------------------
// Kernel 3: output projection (unchanged from R3).
// ---------------------------------------------------------------------------
__global__ __launch_bounds__(256) void oproj_kernel(
    const float* __restrict__ Wo,
    const float* __restrict__ bo,
    float* __restrict__ out)
{
    __shared__ float As[128 * 33];
    __shared__ float Bs[32 * 68];

    const int tid = threadIdx.x;
    const int mt = blockIdx.x;
    const int nt = blockIdx.y;

    const int tm = tid >> 4, tn = tid & 15;
    const int lr = tid >> 3, lc = tid & 7;
    const int br = tid >> 4, bc = tid & 15;

    float acc[8][4];
    #pragma unroll
    for (int i = 0; i < 8; i++)
        #pragma unroll
        for (int j = 0; j < 4; j++) acc[i][j] = 0.f;

    for (int k0 = 0; k0 < 512; k0 += 32) {
        #pragma unroll
        for (int t = 0; t < 4; t++) {
            int m = lr + 32 * t;
            float4 xv = *(const float4*)&g_ctx[(size_t)(mt * 128 + m) * 512 + k0 + lc * 4];
            As[m * 33 + lc * 4 + 0] = xv.x;
            As[m * 33 + lc * 4 + 1] = xv.y;
            As[m * 33 + lc * 4 + 2] = xv.z;
            As[m * 33 + lc * 4 + 3] = xv.w;
        }
        #pragma unroll
        for (int t = 0; t < 2; t++) {
            int k = br + 16 * t;
            float4 wv = *(const float4*)&Wo[(size_t)(k0 + k) * 256 + nt * 64 + bc * 4];
            *(float4*)&Bs[k * 68 + bc * 4] = wv;
        }
        __syncthreads();

        #pragma unroll 8
        for (int kk = 0; kk < 32; kk++) {
            float a[8];
            #pragma unroll
            for (int i = 0; i < 8; i++) a[i] = As[(tm * 8 + i) * 33 + kk];
            float4 bv = *(const float4*)&Bs[kk * 68 + tn * 4];
            #pragma unroll
            for (int i = 0; i < 8; i++) {
                acc[i][0] += a[i] * bv.x;
                acc[i][1] += a[i] * bv.y;
                acc[i][2] += a[i] * bv.z;
                acc[i][3] += a[i] * bv.w;
            }
        }
        __syncthreads();
    }

    float4 bv = *(const float4*)&bo[nt * 64 + tn * 4];
    #pragma unroll
    for (int i = 0; i < 8; i++) {
        int m = mt * 128 + tm * 8 + i;
        float4 r;
        r.x = acc[i][0] + bv.x; r.y = acc[i][1] + bv.y;
        r.z = acc[i][2] + bv.z; r.w = acc[i][3] + bv.w;
        *(float4*)&out[(size_t)m * 256 + nt * 64 + tn * 4] = r;
    }
}

// ---------------------------------------------------------------------------
extern "C" void kernel_launch(void* const* d_in, const int* in_sizes, int n_in,
                              void* d_out, int out_size)
{
    const float* X  = (const float*)d_in[0];
    const float* em = (const float*)d_in[1];
    const float* dw = (const float*)d_in[2];
    const float* Wq = (const float*)d_in[3];
    const float* Wk = (const float*)d_in[4];
    const float* Wv = (const float*)d_in[5];
    const float* Wo = (const float*)d_in[6];
    const float* bo = (const float*)d_in[7];
    float* out = (float*)d_out;

    qkv_kernel  <<<dim3(64, 8, 3), 256>>>(X, Wq, Wk, Wv);
    attn_kernel <<<dim3(8, 8, 8), 256>>>(em, dw);
    oproj_kernel<<<dim3(64, 4, 1), 256>>>(Wo, bo, out);
}

// round 5
// speedup vs baseline: 1.7528x; 1.7528x over previous
#include <cuda_runtime.h>
#include <cuda_bf16.h>
#include <math.h>

// ---------------------------------------------------------------------------
// CrystalGraphAttention  (B=8, N=1024, D=256, H=8, dk=dv=64)
//
//   q,k,v = X @ W{q,k,v}         -> [B,H,N,64]   (kernel 1, fp32 SIMT)
//   flash attention, bf16 m16n8k16 tensor-core, 3-term hi/lo split (kernel 2)
//   out = ctx @ Wo + bo          -> [B,N,256]    (kernel 3, fp32 SIMT)
// ---------------------------------------------------------------------------

#define NEGBIG (-1.0e9f)

static __device__ float g_q [8 * 8 * 1024 * 64];    // [B,H,N,64]
static __device__ float g_k [8 * 8 * 1024 * 64];
static __device__ float g_v [8 * 8 * 1024 * 64];
static __device__ float g_ctx[8 * 1024 * 512];      // [B*N, H*64]

// ---------------------------------------------------------------------------
// Kernel 1: fused QKV projection (unchanged).
// ---------------------------------------------------------------------------
__global__ __launch_bounds__(256) void qkv_kernel(
    const float* __restrict__ X,
    const float* __restrict__ Wq,
    const float* __restrict__ Wk,
    const float* __restrict__ Wv)
{
    __shared__ float As[128 * 33];
    __shared__ float Bs[32 * 68];

    const int tid = threadIdx.x;
    const int mt = blockIdx.x;
    const int h  = blockIdx.y;
    const int w  = blockIdx.z;
    const float* W = (w == 0) ? Wq : (w == 1) ? Wk : Wv;
    float* Out     = (w == 0) ? g_q : (w == 1) ? g_k : g_v;

    const int tm = tid >> 4, tn = tid & 15;
    const int lr = tid >> 3, lc = tid & 7;
    const int br = tid >> 4, bc = tid & 15;

    float acc[8][4];
    #pragma unroll
    for (int i = 0; i < 8; i++)
        #pragma unroll
        for (int j = 0; j < 4; j++) acc[i][j] = 0.f;

    for (int k0 = 0; k0 < 256; k0 += 32) {
        #pragma unroll
        for (int t = 0; t < 4; t++) {
            int m = lr + 32 * t;
            float4 xv = *(const float4*)&X[(size_t)(mt * 128 + m) * 256 + k0 + lc * 4];
            As[m * 33 + lc * 4 + 0] = xv.x;
            As[m * 33 + lc * 4 + 1] = xv.y;
            As[m * 33 + lc * 4 + 2] = xv.z;
            As[m * 33 + lc * 4 + 3] = xv.w;
        }
        #pragma unroll
        for (int t = 0; t < 2; t++) {
            int k = br + 16 * t;
            float4 wv = *(const float4*)&W[(size_t)(k0 + k) * 512 + h * 64 + bc * 4];
            *(float4*)&Bs[k * 68 + bc * 4] = wv;
        }
        __syncthreads();

        #pragma unroll 8
        for (int kk = 0; kk < 32; kk++) {
            float a[8];
            #pragma unroll
            for (int i = 0; i < 8; i++) a[i] = As[(tm * 8 + i) * 33 + kk];
            float4 bv = *(const float4*)&Bs[kk * 68 + tn * 4];
            #pragma unroll
            for (int i = 0; i < 8; i++) {
                acc[i][0] += a[i] * bv.x;
                acc[i][1] += a[i] * bv.y;
                acc[i][2] += a[i] * bv.z;
                acc[i][3] += a[i] * bv.w;
            }
        }
        __syncthreads();
    }

    #pragma unroll
    for (int i = 0; i < 8; i++) {
        int m = mt * 128 + tm * 8 + i;
        int b = m >> 10, s = m & 1023;
        float4 r;
        r.x = acc[i][0]; r.y = acc[i][1]; r.z = acc[i][2]; r.w = acc[i][3];
        *(float4*)&Out[(size_t)((b * 8 + h) * 1024 + s) * 64 + tn * 4] = r;
    }
}

// ---------------------------------------------------------------------------
// bf16 mma helpers
// ---------------------------------------------------------------------------
#define MMA_BF16(c, a, b0, b1)                                              \
    asm volatile(                                                           \
        "mma.sync.aligned.m16n8k16.row.col.f32.bf16.bf16.f32 "              \
        "{%0,%1,%2,%3}, {%4,%5,%6,%7}, {%8,%9}, {%0,%1,%2,%3};"             \
        : "+f"((c)[0]), "+f"((c)[1]), "+f"((c)[2]), "+f"((c)[3])            \
        : "r"((a)[0]), "r"((a)[1]), "r"((a)[2]), "r"((a)[3]),               \
          "r"(b0), "r"(b1))

// pack two floats -> bf16x2 (low half = x, high half = y)
__device__ __forceinline__ unsigned pack_bf2(float x, float y)
{
    unsigned r;
    asm("cvt.rn.bf16x2.f32 %0, %1, %2;" : "=r"(r) : "f"(y), "f"(x));
    return r;
}

__device__ __forceinline__ float bf16_hi_f(float x)
{
    return __bfloat162float(__float2bfloat16(x));
}

// ---------------------------------------------------------------------------
// Kernel 2: flash attention, bf16 tensor-core 3-term split.
// grid = (8 qtiles, 8 heads, 8 batches), block = 256 (8 warps).
// Q-tile = 128 rows (16/warp, register-resident packed bf16 hi/lo fragments,
// 1/8 scale folded in).  K-tile = 64 keys.
// Smem: K pre-split hi/lo as [key][dpair] (uint = bf16x2), V pre-split and
// TRANSPOSED hi/lo as [d][keypair]; stride 36 uints -> B-frag LDS addresses
// g*4+tg cover all 32 banks (conflict-free).
// m16n8k16 frag maps (g = lane>>2, tg = lane&3):
//   A: a0=(g,2tg..+1) a1=(g+8,2tg..) a2=(g,2tg+8..) a3=(g+8,2tg+8..)  [bf16x2]
//   B: b0=(k=2tg..+1, n=g)  b1=(k=2tg+8..+1, n=g)                     [bf16x2]
//   C: c0=(g,2tg) c1=(g,2tg+1) c2=(g+8,2tg) c3=(g+8,2tg+1)
// Key identity: C-frag of S == A-frag of P for the PV mma (no repack shuffles).
// ---------------------------------------------------------------------------
__global__ __launch_bounds__(256, 1) void attn_kernel(
    const float* __restrict__ em,     // [B,1,N,N]
    const float* __restrict__ dw)     // [B,N]
{
    __shared__ unsigned KsHi[64 * 36];   // [key][dpair]
    __shared__ unsigned KsLo[64 * 36];
    __shared__ unsigned VtHi[64 * 36];   // [d][keypair]
    __shared__ unsigned VtLo[64 * 36];

    const int tid  = threadIdx.x;
    const int wid  = tid >> 5;
    const int lane = tid & 31;
    const int g    = lane >> 2;
    const int tg   = lane & 3;
    const int qt = blockIdx.x, h = blockIdx.y, b = blockIdx.z;
    const int qrow0 = qt * 128 + wid * 16;

    const float* qb = &g_q[(size_t)((b * 8 + h) * 1024 + qrow0) * 64];
    const float* kb = &g_k[(size_t)(b * 8 + h) * 1024 * 64];
    const float* vb = &g_v[(size_t)(b * 8 + h) * 1024 * 64];
    const float* emb = em + (size_t)b * 1024 * 1024;
    const float* dwb = dw + b * 1024;

    // ---- Q fragments (scaled by 1/8), packed bf16x2 hi/lo, resident ----
    unsigned qhi[4][4], qlo[4][4];
    #pragma unroll
    for (int kc = 0; kc < 4; kc++) {
        #pragma unroll
        for (int j = 0; j < 4; j++) {
            int row = (j & 1) ? g + 8 : g;
            int col = kc * 16 + 2 * tg + ((j >> 1) ? 8 : 0);
            float2 qv = *(const float2*)&qb[(size_t)row * 64 + col];
            qv.x *= 0.125f; qv.y *= 0.125f;
            float hx = bf16_hi_f(qv.x), hy = bf16_hi_f(qv.y);
            qhi[kc][j] = pack_bf2(hx, hy);
            qlo[kc][j] = pack_bf2(qv.x - hx, qv.y - hy);
        }
    }

    float O[8][4];
    #pragma unroll
    for (int nt = 0; nt < 8; nt++)
        #pragma unroll
        for (int j = 0; j < 4; j++) O[nt][j] = 0.f;
    float mi0 = -1e30f, mi1 = -1e30f, li0 = 0.f, li1 = 0.f;

    __nv_bfloat16* VtHi16 = (__nv_bfloat16*)VtHi;
    __nv_bfloat16* VtLo16 = (__nv_bfloat16*)VtLo;

    for (int kt = 0; kt < 16; kt++) {
        __syncthreads();
        // ---- stage K (hi/lo split) and V (split + transposed) ----
        {
            int r = tid >> 4;                 // key row base
            int c = (tid & 15) * 4;           // d base
            #pragma unroll
            for (int t = 0; t < 4; t++, r += 16) {
                float4 kv = *(const float4*)&kb[(size_t)(kt * 64 + r) * 64 + c];
                float h0 = bf16_hi_f(kv.x), h1 = bf16_hi_f(kv.y);
                float h2 = bf16_hi_f(kv.z), h3 = bf16_hi_f(kv.w);
                KsHi[r * 36 + c / 2]     = pack_bf2(h0, h1);
                KsHi[r * 36 + c / 2 + 1] = pack_bf2(h2, h3);
                KsLo[r * 36 + c / 2]     = pack_bf2(kv.x - h0, kv.y - h1);
                KsLo[r * 36 + c / 2 + 1] = pack_bf2(kv.z - h2, kv.w - h3);

                float4 vv = *(const float4*)&vb[(size_t)(kt * 64 + r) * 64 + c];
                float v0 = bf16_hi_f(vv.x), v1 = bf16_hi_f(vv.y);
                float v2 = bf16_hi_f(vv.z), v3 = bf16_hi_f(vv.w);
                VtHi16[(c + 0) * 72 + r] = __float2bfloat16(v0);
                VtHi16[(c + 1) * 72 + r] = __float2bfloat16(v1);
                VtHi16[(c + 2) * 72 + r] = __float2bfloat16(v2);
                VtHi16[(c + 3) * 72 + r] = __float2bfloat16(v3);
                VtLo16[(c + 0) * 72 + r] = __float2bfloat16(vv.x - v0);
                VtLo16[(c + 1) * 72 + r] = __float2bfloat16(vv.y - v1);
                VtLo16[(c + 2) * 72 + r] = __float2bfloat16(vv.z - v2);
                VtLo16[(c + 3) * 72 + r] = __float2bfloat16(vv.w - v3);
            }
        }

        // ---- prefetch mask + distance weights (overlaps with MMAs) ----
        float2 mk0[8], mk1[8], dv2[8];
        {
            const float* er0 = emb + (size_t)(qrow0 + g) * 1024 + kt * 64;
            const float* er1 = er0 + (size_t)8 * 1024;
            const float* dr  = dwb + kt * 64;
            #pragma unroll
            for (int nt = 0; nt < 8; nt++) {
                mk0[nt] = *(const float2*)&er0[nt * 8 + 2 * tg];
                mk1[nt] = *(const float2*)&er1[nt * 8 + 2 * tg];
                dv2[nt] = *(const float2*)&dr [nt * 8 + 2 * tg];
            }
        }
        __syncthreads();

        // ---- S = (Q/8) K^T  (3-term bf16) ----
        float S[8][4];
        #pragma unroll
        for (int nt = 0; nt < 8; nt++) {
            S[nt][0] = S[nt][1] = S[nt][2] = S[nt][3] = 0.f;
            #pragma unroll
            for (int kc = 0; kc < 4; kc++) {
                int base = (nt * 8 + g) * 36 + kc * 8 + tg;
                unsigned b0h = KsHi[base], b1h = KsHi[base + 4];
                unsigned b0l = KsLo[base], b1l = KsLo[base + 4];
                MMA_BF16(S[nt], qhi[kc], b0h, b1h);
                MMA_BF16(S[nt], qhi[kc], b0l, b1l);
                MMA_BF16(S[nt], qlo[kc], b0h, b1h);
            }
        }

        // ---- mask + distance modulation + online softmax ----
        float rm0 = -1e30f, rm1 = -1e30f;
        #pragma unroll
        for (int nt = 0; nt < 8; nt++) {
            float l0 = (S[nt][0] + (1.f - mk0[nt].x) * NEGBIG) * dv2[nt].x;
            float l1 = (S[nt][1] + (1.f - mk0[nt].y) * NEGBIG) * dv2[nt].y;
            float l2 = (S[nt][2] + (1.f - mk1[nt].x) * NEGBIG) * dv2[nt].x;
            float l3 = (S[nt][3] + (1.f - mk1[nt].y) * NEGBIG) * dv2[nt].y;
            S[nt][0] = l0; S[nt][1] = l1; S[nt][2] = l2; S[nt][3] = l3;
            rm0 = fmaxf(rm0, fmaxf(l0, l1));
            rm1 = fmaxf(rm1, fmaxf(l2, l3));
        }
        #pragma unroll
        for (int off = 1; off <= 2; off <<= 1) {
            rm0 = fmaxf(rm0, __shfl_xor_sync(0xffffffffu, rm0, off));
            rm1 = fmaxf(rm1, __shfl_xor_sync(0xffffffffu, rm1, off));
        }
        float nm0 = fmaxf(mi0, rm0), nm1 = fmaxf(mi1, rm1);
        float corr0 = __expf(mi0 - nm0), corr1 = __expf(mi1 - nm1);

        float rs0 = 0.f, rs1 = 0.f;
        #pragma unroll
        for (int nt = 0; nt < 8; nt++) {
            float p0 = __expf(S[nt][0] - nm0);
            float p1 = __expf(S[nt][1] - nm0);
            float p2 = __expf(S[nt][2] - nm1);
            float p3 = __expf(S[nt][3] - nm1);
            S[nt][0] = p0; S[nt][1] = p1; S[nt][2] = p2; S[nt][3] = p3;
            rs0 += p0 + p1; rs1 += p2 + p3;
        }
        #pragma unroll
        for (int off = 1; off <= 2; off <<= 1) {
            rs0 += __shfl_xor_sync(0xffffffffu, rs0, off);
            rs1 += __shfl_xor_sync(0xffffffffu, rs1, off);
        }
        li0 = li0 * corr0 + rs0;  mi0 = nm0;
        li1 = li1 * corr1 + rs1;  mi1 = nm1;
        #pragma unroll
        for (int nt = 0; nt < 8; nt++) {
            O[nt][0] *= corr0; O[nt][1] *= corr0;
            O[nt][2] *= corr1; O[nt][3] *= corr1;
        }

        // ---- O += P V  (3-term bf16; P A-frags come straight from S) ----
        #pragma unroll
        for (int kc = 0; kc < 4; kc++) {
            // A-frag of P for key chunk kc*16..+15:
            //   a0 = S[2kc][0..1], a1 = S[2kc][2..3],
            //   a2 = S[2kc+1][0..1], a3 = S[2kc+1][2..3]
            unsigned pa_h[4], pa_l[4];
            #pragma unroll
            for (int j = 0; j < 4; j++) {
                float x = S[2 * kc + (j >> 1)][(j & 1) ? 2 : 0];
                float y = S[2 * kc + (j >> 1)][(j & 1) ? 3 : 1];
                float hx = bf16_hi_f(x), hy = bf16_hi_f(y);
                pa_h[j] = pack_bf2(hx, hy);
                pa_l[j] = pack_bf2(x - hx, y - hy);
            }
            #pragma unroll
            for (int nt = 0; nt < 8; nt++) {
                int base = (nt * 8 + g) * 36 + kc * 8 + tg;
                unsigned b0h = VtHi[base], b1h = VtHi[base + 4];
                unsigned b0l = VtLo[base], b1l = VtLo[base + 4];
                MMA_BF16(O[nt], pa_h, b0h, b1h);
                MMA_BF16(O[nt], pa_h, b0l, b1l);
                MMA_BF16(O[nt], pa_l, b0h, b1h);
            }
        }
    }

    // ---- epilogue: normalize and write ctx ----
    float inv0 = 1.f / li0, inv1 = 1.f / li1;
    #pragma unroll
    for (int nt = 0; nt < 8; nt++) {
        float2 r0, r1;
        r0.x = O[nt][0] * inv0; r0.y = O[nt][1] * inv0;
        r1.x = O[nt][2] * inv1; r1.y = O[nt][3] * inv1;
        *(float2*)&g_ctx[(size_t)(b * 1024 + qrow0 + g) * 512
                         + h * 64 + nt * 8 + 2 * tg] = r0;
        *(float2*)&g_ctx[(size_t)(b * 1024 + qrow0 + g + 8) * 512
                         + h * 64 + nt * 8 + 2 * tg] = r1;
    }
}

// ---------------------------------------------------------------------------
// Kernel 3: output projection (unchanged).
// ---------------------------------------------------------------------------
__global__ __launch_bounds__(256) void oproj_kernel(
    const float* __restrict__ Wo,
    const float* __restrict__ bo,
    float* __restrict__ out)
{
    __shared__ float As[128 * 33];
    __shared__ float Bs[32 * 68];

    const int tid = threadIdx.x;
    const int mt = blockIdx.x;
    const int nt = blockIdx.y;

    const int tm = tid >> 4, tn = tid & 15;
    const int lr = tid >> 3, lc = tid & 7;
    const int br = tid >> 4, bc = tid & 15;

    float acc[8][4];
    #pragma unroll
    for (int i = 0; i < 8; i++)
        #pragma unroll
        for (int j = 0; j < 4; j++) acc[i][j] = 0.f;

    for (int k0 = 0; k0 < 512; k0 += 32) {
        #pragma unroll
        for (int t = 0; t < 4; t++) {
            int m = lr + 32 * t;
            float4 xv = *(const float4*)&g_ctx[(size_t)(mt * 128 + m) * 512 + k0 + lc * 4];
            As[m * 33 + lc * 4 + 0] = xv.x;
            As[m * 33 + lc * 4 + 1] = xv.y;
            As[m * 33 + lc * 4 + 2] = xv.z;
            As[m * 33 + lc * 4 + 3] = xv.w;
        }
        #pragma unroll
        for (int t = 0; t < 2; t++) {
            int k = br + 16 * t;
            float4 wv = *(const float4*)&Wo[(size_t)(k0 + k) * 256 + nt * 64 + bc * 4];
            *(float4*)&Bs[k * 68 + bc * 4] = wv;
        }
        __syncthreads();

        #pragma unroll 8
        for (int kk = 0; kk < 32; kk++) {
            float a[8];
            #pragma unroll
            for (int i = 0; i < 8; i++) a[i] = As[(tm * 8 + i) * 33 + kk];
            float4 bv = *(const float4*)&Bs[kk * 68 + tn * 4];
            #pragma unroll
            for (int i = 0; i < 8; i++) {
                acc[i][0] += a[i] * bv.x;
                acc[i][1] += a[i] * bv.y;
                acc[i][2] += a[i] * bv.z;
                acc[i][3] += a[i] * bv.w;
            }
        }
        __syncthreads();
    }

    float4 bv = *(const float4*)&bo[nt * 64 + tn * 4];
    #pragma unroll
    for (int i = 0; i < 8; i++) {
        int m = mt * 128 + tm * 8 + i;
        float4 r;
        r.x = acc[i][0] + bv.x; r.y = acc[i][1] + bv.y;
        r.z = acc[i][2] + bv.z; r.w = acc[i][3] + bv.w;
        *(float4*)&out[(size_t)m * 256 + nt * 64 + tn * 4] = r;
    }
}

// ---------------------------------------------------------------------------
extern "C" void kernel_launch(void* const* d_in, const int* in_sizes, int n_in,
                              void* d_out, int out_size)
{
    const float* X  = (const float*)d_in[0];
    const float* em = (const float*)d_in[1];
    const float* dw = (const float*)d_in[2];
    const float* Wq = (const float*)d_in[3];
    const float* Wk = (const float*)d_in[4];
    const float* Wv = (const float*)d_in[5];
    const float* Wo = (const float*)d_in[6];
    const float* bo = (const float*)d_in[7];
    float* out = (float*)d_out;

    qkv_kernel  <<<dim3(64, 8, 3), 256>>>(X, Wq, Wk, Wv);
    attn_kernel <<<dim3(8, 8, 8), 256>>>(em, dw);
    oproj_kernel<<<dim3(64, 4, 1), 256>>>(Wo, bo, out);
}

// round 6
// speedup vs baseline: 2.2531x; 1.2854x over previous
#include <cuda_runtime.h>
#include <cuda_bf16.h>
#include <math.h>

// ---------------------------------------------------------------------------
// CrystalGraphAttention  (B=8, N=1024, D=256, H=8, dk=dv=64)
//
//   q,k,v = X @ W{q,k,v}   (kernel 1, bf16 m16n8k16 3-term)
//   flash attention        (kernel 2, bf16 m16n8k16 3-term)
//   out = ctx @ Wo + bo    (kernel 3, bf16 m16n8k16 3-term)
// ---------------------------------------------------------------------------

#define NEGBIG (-1.0e9f)

static __device__ float g_q [8 * 8 * 1024 * 64];    // [B,H,N,64]
static __device__ float g_k [8 * 8 * 1024 * 64];
static __device__ float g_v [8 * 8 * 1024 * 64];
static __device__ float g_ctx[8 * 1024 * 512];      // [B*N, H*64]

// ---------------------------------------------------------------------------
// bf16 mma helpers
// ---------------------------------------------------------------------------
#define MMA_BF16(c, a, b0, b1)                                              \
    asm volatile(                                                           \
        "mma.sync.aligned.m16n8k16.row.col.f32.bf16.bf16.f32 "              \
        "{%0,%1,%2,%3}, {%4,%5,%6,%7}, {%8,%9}, {%0,%1,%2,%3};"             \
        : "+f"((c)[0]), "+f"((c)[1]), "+f"((c)[2]), "+f"((c)[3])            \
        : "r"((a)[0]), "r"((a)[1]), "r"((a)[2]), "r"((a)[3]),               \
          "r"(b0), "r"(b1))

__device__ __forceinline__ unsigned pack_bf2(float x, float y)
{
    unsigned r;
    asm("cvt.rn.bf16x2.f32 %0, %1, %2;" : "=r"(r) : "f"(y), "f"(x));
    return r;
}

__device__ __forceinline__ float bf16_hi_f(float x)
{
    return __bfloat162float(__float2bfloat16(x));
}

// ---------------------------------------------------------------------------
// Kernel 1: QKV projection, bf16 tensor-core 3-term.
// grid = (64 mtiles, 8 heads, 3 weights), block = 256 (8 warps).
// C-tile 128x64 (16 rows/warp).  K staged in steps of 32.
// W staged hi/lo as [kpair][n], stride 72 uints:
//   read bank = 8*tg + g (all 32);  writes are uint4, phase-complete.
// ---------------------------------------------------------------------------
__global__ __launch_bounds__(256, 1) void qkv_kernel(
    const float* __restrict__ X,
    const float* __restrict__ Wq,
    const float* __restrict__ Wk,
    const float* __restrict__ Wv)
{
    __shared__ __align__(16) unsigned Whi[16 * 72];
    __shared__ __align__(16) unsigned Wlo[16 * 72];

    const int tid  = threadIdx.x;
    const int wid  = tid >> 5;
    const int lane = tid & 31;
    const int g    = lane >> 2;
    const int tg   = lane & 3;
    const int mt = blockIdx.x, h = blockIdx.y, w = blockIdx.z;
    const float* W = (w == 0) ? Wq : (w == 1) ? Wk : Wv;
    float* Out     = (w == 0) ? g_q : (w == 1) ? g_k : g_v;

    const int mrow0 = mt * 128 + wid * 16;
    const float* arow0 = &X[(size_t)(mrow0 + g) * 256];
    const float* arow1 = arow0 + 8 * 256;

    const int kp = tid >> 4;              // 0..15 (k-pair for staging)
    const int n4 = (tid & 15) * 4;        // n base for staging

    float C[8][4];
    #pragma unroll
    for (int nt = 0; nt < 8; nt++)
        #pragma unroll
        for (int j = 0; j < 4; j++) C[nt][j] = 0.f;

    for (int k0 = 0; k0 < 256; k0 += 32) {
        __syncthreads();
        // ---- stage W chunk [32 x 64] hi/lo ----
        {
            const float* wr0 = &W[(size_t)(k0 + 2 * kp) * 512 + h * 64 + n4];
            const float* wr1 = wr0 + 512;
            float4 w0 = *(const float4*)wr0;
            float4 w1 = *(const float4*)wr1;
            float h0x = bf16_hi_f(w0.x), h1x = bf16_hi_f(w1.x);
            float h0y = bf16_hi_f(w0.y), h1y = bf16_hi_f(w1.y);
            float h0z = bf16_hi_f(w0.z), h1z = bf16_hi_f(w1.z);
            float h0w = bf16_hi_f(w0.w), h1w = bf16_hi_f(w1.w);
            uint4 hi4, lo4;
            hi4.x = pack_bf2(h0x, h1x);
            hi4.y = pack_bf2(h0y, h1y);
            hi4.z = pack_bf2(h0z, h1z);
            hi4.w = pack_bf2(h0w, h1w);
            lo4.x = pack_bf2(w0.x - h0x, w1.x - h1x);
            lo4.y = pack_bf2(w0.y - h0y, w1.y - h1y);
            lo4.z = pack_bf2(w0.z - h0z, w1.z - h1z);
            lo4.w = pack_bf2(w0.w - h0w, w1.w - h1w);
            *(uint4*)&Whi[kp * 72 + n4] = hi4;
            *(uint4*)&Wlo[kp * 72 + n4] = lo4;
        }
        __syncthreads();

        #pragma unroll
        for (int kc = 0; kc < 2; kc++) {
            // ---- A fragment (hi/lo) direct from gmem ----
            unsigned ahi[4], alo[4];
            {
                int col = k0 + kc * 16 + 2 * tg;
                float2 a0 = *(const float2*)&arow0[col];
                float2 a1 = *(const float2*)&arow1[col];
                float2 a2 = *(const float2*)&arow0[col + 8];
                float2 a3 = *(const float2*)&arow1[col + 8];
                float hx, hy;
                hx = bf16_hi_f(a0.x); hy = bf16_hi_f(a0.y);
                ahi[0] = pack_bf2(hx, hy); alo[0] = pack_bf2(a0.x - hx, a0.y - hy);
                hx = bf16_hi_f(a1.x); hy = bf16_hi_f(a1.y);
                ahi[1] = pack_bf2(hx, hy); alo[1] = pack_bf2(a1.x - hx, a1.y - hy);
                hx = bf16_hi_f(a2.x); hy = bf16_hi_f(a2.y);
                ahi[2] = pack_bf2(hx, hy); alo[2] = pack_bf2(a2.x - hx, a2.y - hy);
                hx = bf16_hi_f(a3.x); hy = bf16_hi_f(a3.y);
                ahi[3] = pack_bf2(hx, hy); alo[3] = pack_bf2(a3.x - hx, a3.y - hy);
            }
            #pragma unroll
            for (int nt = 0; nt < 8; nt++) {
                int base = (kc * 8 + tg) * 72 + nt * 8 + g;
                unsigned b0h = Whi[base], b1h = Whi[base + 4 * 72];
                unsigned b0l = Wlo[base], b1l = Wlo[base + 4 * 72];
                MMA_BF16(C[nt], ahi, b0h, b1h);
                MMA_BF16(C[nt], ahi, b0l, b1l);
                MMA_BF16(C[nt], alo, b0h, b1h);
            }
        }
    }

    // ---- write to [B,H,N,64] ----
    #pragma unroll
    for (int nt = 0; nt < 8; nt++) {
        int m0 = mrow0 + g;
        int m1 = m0 + 8;
        int b0i = m0 >> 10, s0 = m0 & 1023;
        int b1i = m1 >> 10, s1 = m1 & 1023;
        float2 r0, r1;
        r0.x = C[nt][0]; r0.y = C[nt][1];
        r1.x = C[nt][2]; r1.y = C[nt][3];
        *(float2*)&Out[(size_t)((b0i * 8 + h) * 1024 + s0) * 64 + nt * 8 + 2 * tg] = r0;
        *(float2*)&Out[(size_t)((b1i * 8 + h) * 1024 + s1) * 64 + nt * 8 + 2 * tg] = r1;
    }
}

// ---------------------------------------------------------------------------
// Kernel 2: flash attention, bf16 tensor-core 3-term.
// grid = (8 qtiles, 8 heads, 8 batches), block = 256 (8 warps).
// K smem [key][dpair] stride 36 (read bank 4g+tg, conflict-free; uint2 writes).
// V smem transposed [d][keypair] stride 40 (read bank 8g+tg; writes bank kp+c,
// both conflict-free).
// ---------------------------------------------------------------------------
__global__ __launch_bounds__(256, 1) void attn_kernel(
    const float* __restrict__ em,     // [B,1,N,N]
    const float* __restrict__ dw)     // [B,N]
{
    __shared__ __align__(16) unsigned KsHi[64 * 36];   // [key][dpair]
    __shared__ __align__(16) unsigned KsLo[64 * 36];
    __shared__ __align__(16) unsigned VtHi[64 * 40];   // [d][keypair]
    __shared__ __align__(16) unsigned VtLo[64 * 40];

    const int tid  = threadIdx.x;
    const int wid  = tid >> 5;
    const int lane = tid & 31;
    const int g    = lane >> 2;
    const int tg   = lane & 3;
    const int qt = blockIdx.x, h = blockIdx.y, b = blockIdx.z;
    const int qrow0 = qt * 128 + wid * 16;

    const float* qb = &g_q[(size_t)((b * 8 + h) * 1024 + qrow0) * 64];
    const float* kb = &g_k[(size_t)(b * 8 + h) * 1024 * 64];
    const float* vb = &g_v[(size_t)(b * 8 + h) * 1024 * 64];
    const float* emb = em + (size_t)b * 1024 * 1024;
    const float* dwb = dw + b * 1024;

    // ---- Q fragments (scaled by 1/8), packed bf16x2 hi/lo, resident ----
    unsigned qhi[4][4], qlo[4][4];
    #pragma unroll
    for (int kc = 0; kc < 4; kc++) {
        #pragma unroll
        for (int j = 0; j < 4; j++) {
            int row = (j & 1) ? g + 8 : g;
            int col = kc * 16 + 2 * tg + ((j >> 1) ? 8 : 0);
            float2 qv = *(const float2*)&qb[(size_t)row * 64 + col];
            qv.x *= 0.125f; qv.y *= 0.125f;
            float hx = bf16_hi_f(qv.x), hy = bf16_hi_f(qv.y);
            qhi[kc][j] = pack_bf2(hx, hy);
            qlo[kc][j] = pack_bf2(qv.x - hx, qv.y - hy);
        }
    }

    float O[8][4];
    #pragma unroll
    for (int nt = 0; nt < 8; nt++)
        #pragma unroll
        for (int j = 0; j < 4; j++) O[nt][j] = 0.f;
    float mi0 = -1e30f, mi1 = -1e30f, li0 = 0.f, li1 = 0.f;

    // staging thread maps
    const int kr = tid >> 4;            // K: key row base (0..15)
    const int kc4 = (tid & 15) * 4;     // K: d base
    const int vkp = tid & 31;           // V: keypair (0..31)
    const int vd0 = (tid >> 5) * 8;     // V: d group base

    for (int kt = 0; kt < 16; kt++) {
        __syncthreads();
        // ---- stage K (hi/lo, [key][dpair]) ----
        {
            int r = kr;
            #pragma unroll
            for (int t = 0; t < 4; t++, r += 16) {
                float4 kv = *(const float4*)&kb[(size_t)(kt * 64 + r) * 64 + kc4];
                float h0 = bf16_hi_f(kv.x), h1 = bf16_hi_f(kv.y);
                float h2 = bf16_hi_f(kv.z), h3 = bf16_hi_f(kv.w);
                uint2 hp, lp;
                hp.x = pack_bf2(h0, h1);          hp.y = pack_bf2(h2, h3);
                lp.x = pack_bf2(kv.x - h0, kv.y - h1);
                lp.y = pack_bf2(kv.z - h2, kv.w - h3);
                *(uint2*)&KsHi[r * 36 + kc4 / 2] = hp;
                *(uint2*)&KsLo[r * 36 + kc4 / 2] = lp;
            }
        }
        // ---- stage V transposed (hi/lo, [d][keypair]) ----
        {
            const float* vr0 = &vb[(size_t)(kt * 64 + 2 * vkp) * 64 + vd0];
            const float* vr1 = vr0 + 64;
            float e0[8], e1[8];
            float4 t0 = *(const float4*)&vr0[0];
            float4 t1 = *(const float4*)&vr0[4];
            float4 u0 = *(const float4*)&vr1[0];
            float4 u1 = *(const float4*)&vr1[4];
            e0[0]=t0.x; e0[1]=t0.y; e0[2]=t0.z; e0[3]=t0.w;
            e0[4]=t1.x; e0[5]=t1.y; e0[6]=t1.z; e0[7]=t1.w;
            e1[0]=u0.x; e1[1]=u0.y; e1[2]=u0.z; e1[3]=u0.w;
            e1[4]=u1.x; e1[5]=u1.y; e1[6]=u1.z; e1[7]=u1.w;
            #pragma unroll
            for (int i = 0; i < 8; i++) {
                float h0 = bf16_hi_f(e0[i]), h1 = bf16_hi_f(e1[i]);
                VtHi[(vd0 + i) * 40 + vkp] = pack_bf2(h0, h1);
                VtLo[(vd0 + i) * 40 + vkp] = pack_bf2(e0[i] - h0, e1[i] - h1);
            }
        }

        // ---- prefetch mask + distance weights (overlaps with MMAs) ----
        float2 mk0[8], mk1[8], dv2[8];
        {
            const float* er0 = emb + (size_t)(qrow0 + g) * 1024 + kt * 64;
            const float* er1 = er0 + (size_t)8 * 1024;
            const float* dr  = dwb + kt * 64;
            #pragma unroll
            for (int nt = 0; nt < 8; nt++) {
                mk0[nt] = *(const float2*)&er0[nt * 8 + 2 * tg];
                mk1[nt] = *(const float2*)&er1[nt * 8 + 2 * tg];
                dv2[nt] = *(const float2*)&dr [nt * 8 + 2 * tg];
            }
        }
        __syncthreads();

        // ---- S = (Q/8) K^T  (3-term bf16) ----
        float S[8][4];
        #pragma unroll
        for (int nt = 0; nt < 8; nt++) {
            S[nt][0] = S[nt][1] = S[nt][2] = S[nt][3] = 0.f;
            #pragma unroll
            for (int kc = 0; kc < 4; kc++) {
                int base = (nt * 8 + g) * 36 + kc * 8 + tg;
                unsigned b0h = KsHi[base], b1h = KsHi[base + 4];
                unsigned b0l = KsLo[base], b1l = KsLo[base + 4];
                MMA_BF16(S[nt], qhi[kc], b0h, b1h);
                MMA_BF16(S[nt], qhi[kc], b0l, b1l);
                MMA_BF16(S[nt], qlo[kc], b0h, b1h);
            }
        }

        // ---- mask + distance modulation + online softmax ----
        float rm0 = -1e30f, rm1 = -1e30f;
        #pragma unroll
        for (int nt = 0; nt < 8; nt++) {
            float l0 = (S[nt][0] + (1.f - mk0[nt].x) * NEGBIG) * dv2[nt].x;
            float l1 = (S[nt][1] + (1.f - mk0[nt].y) * NEGBIG) * dv2[nt].y;
            float l2 = (S[nt][2] + (1.f - mk1[nt].x) * NEGBIG) * dv2[nt].x;
            float l3 = (S[nt][3] + (1.f - mk1[nt].y) * NEGBIG) * dv2[nt].y;
            S[nt][0] = l0; S[nt][1] = l1; S[nt][2] = l2; S[nt][3] = l3;
            rm0 = fmaxf(rm0, fmaxf(l0, l1));
            rm1 = fmaxf(rm1, fmaxf(l2, l3));
        }
        #pragma unroll
        for (int off = 1; off <= 2; off <<= 1) {
            rm0 = fmaxf(rm0, __shfl_xor_sync(0xffffffffu, rm0, off));
            rm1 = fmaxf(rm1, __shfl_xor_sync(0xffffffffu, rm1, off));
        }
        float nm0 = fmaxf(mi0, rm0), nm1 = fmaxf(mi1, rm1);
        float corr0 = __expf(mi0 - nm0), corr1 = __expf(mi1 - nm1);

        float rs0 = 0.f, rs1 = 0.f;
        #pragma unroll
        for (int nt = 0; nt < 8; nt++) {
            float p0 = __expf(S[nt][0] - nm0);
            float p1 = __expf(S[nt][1] - nm0);
            float p2 = __expf(S[nt][2] - nm1);
            float p3 = __expf(S[nt][3] - nm1);
            S[nt][0] = p0; S[nt][1] = p1; S[nt][2] = p2; S[nt][3] = p3;
            rs0 += p0 + p1; rs1 += p2 + p3;
        }
        #pragma unroll
        for (int off = 1; off <= 2; off <<= 1) {
            rs0 += __shfl_xor_sync(0xffffffffu, rs0, off);
            rs1 += __shfl_xor_sync(0xffffffffu, rs1, off);
        }
        li0 = li0 * corr0 + rs0;  mi0 = nm0;
        li1 = li1 * corr1 + rs1;  mi1 = nm1;
        #pragma unroll
        for (int nt = 0; nt < 8; nt++) {
            O[nt][0] *= corr0; O[nt][1] *= corr0;
            O[nt][2] *= corr1; O[nt][3] *= corr1;
        }

        // ---- O += P V  (3-term bf16; P A-frags come straight from S) ----
        #pragma unroll
        for (int kc = 0; kc < 4; kc++) {
            unsigned pa_h[4], pa_l[4];
            #pragma unroll
            for (int j = 0; j < 4; j++) {
                float x = S[2 * kc + (j >> 1)][(j & 1) ? 2 : 0];
                float y = S[2 * kc + (j >> 1)][(j & 1) ? 3 : 1];
                float hx = bf16_hi_f(x), hy = bf16_hi_f(y);
                pa_h[j] = pack_bf2(hx, hy);
                pa_l[j] = pack_bf2(x - hx, y - hy);
            }
            #pragma unroll
            for (int nt = 0; nt < 8; nt++) {
                int base = (nt * 8 + g) * 40 + kc * 8 + tg;
                unsigned b0h = VtHi[base], b1h = VtHi[base + 4];
                unsigned b0l = VtLo[base], b1l = VtLo[base + 4];
                MMA_BF16(O[nt], pa_h, b0h, b1h);
                MMA_BF16(O[nt], pa_h, b0l, b1l);
                MMA_BF16(O[nt], pa_l, b0h, b1h);
            }
        }
    }

    // ---- epilogue: normalize and write ctx ----
    float inv0 = 1.f / li0, inv1 = 1.f / li1;
    #pragma unroll
    for (int nt = 0; nt < 8; nt++) {
        float2 r0, r1;
        r0.x = O[nt][0] * inv0; r0.y = O[nt][1] * inv0;
        r1.x = O[nt][2] * inv1; r1.y = O[nt][3] * inv1;
        *(float2*)&g_ctx[(size_t)(b * 1024 + qrow0 + g) * 512
                         + h * 64 + nt * 8 + 2 * tg] = r0;
        *(float2*)&g_ctx[(size_t)(b * 1024 + qrow0 + g + 8) * 512
                         + h * 64 + nt * 8 + 2 * tg] = r1;
    }
}

// ---------------------------------------------------------------------------
// Kernel 3: output projection, bf16 tensor-core 3-term.
// grid = (64 mtiles, 4 ntiles), block = 256.  K=512, same scheme as kernel 1.
// ---------------------------------------------------------------------------
__global__ __launch_bounds__(256, 1) void oproj_kernel(
    const float* __restrict__ Wo,
    const float* __restrict__ bo,
    float* __restrict__ out)
{
    __shared__ __align__(16) unsigned Whi[16 * 72];
    __shared__ __align__(16) unsigned Wlo[16 * 72];

    const int tid  = threadIdx.x;
    const int wid  = tid >> 5;
    const int lane = tid & 31;
    const int g    = lane >> 2;
    const int tg   = lane & 3;
    const int mt = blockIdx.x;
    const int ntile = blockIdx.y;
    const int noff = ntile * 64;

    const int mrow0 = mt * 128 + wid * 16;
    const float* arow0 = &g_ctx[(size_t)(mrow0 + g) * 512];
    const float* arow1 = arow0 + 8 * 512;

    const int kp = tid >> 4;
    const int n4 = (tid & 15) * 4;

    float C[8][4];
    #pragma unroll
    for (int nt = 0; nt < 8; nt++)
        #pragma unroll
        for (int j = 0; j < 4; j++) C[nt][j] = 0.f;

    for (int k0 = 0; k0 < 512; k0 += 32) {
        __syncthreads();
        {
            const float* wr0 = &Wo[(size_t)(k0 + 2 * kp) * 256 + noff + n4];
            const float* wr1 = wr0 + 256;
            float4 w0 = *(const float4*)wr0;
            float4 w1 = *(const float4*)wr1;
            float h0x = bf16_hi_f(w0.x), h1x = bf16_hi_f(w1.x);
            float h0y = bf16_hi_f(w0.y), h1y = bf16_hi_f(w1.y);
            float h0z = bf16_hi_f(w0.z), h1z = bf16_hi_f(w1.z);
            float h0w = bf16_hi_f(w0.w), h1w = bf16_hi_f(w1.w);
            uint4 hi4, lo4;
            hi4.x = pack_bf2(h0x, h1x);
            hi4.y = pack_bf2(h0y, h1y);
            hi4.z = pack_bf2(h0z, h1z);
            hi4.w = pack_bf2(h0w, h1w);
            lo4.x = pack_bf2(w0.x - h0x, w1.x - h1x);
            lo4.y = pack_bf2(w0.y - h0y, w1.y - h1y);
            lo4.z = pack_bf2(w0.z - h0z, w1.z - h1z);
            lo4.w = pack_bf2(w0.w - h0w, w1.w - h1w);
            *(uint4*)&Whi[kp * 72 + n4] = hi4;
            *(uint4*)&Wlo[kp * 72 + n4] = lo4;
        }
        __syncthreads();

        #pragma unroll
        for (int kc = 0; kc < 2; kc++) {
            unsigned ahi[4], alo[4];
            {
                int col = k0 + kc * 16 + 2 * tg;
                float2 a0 = *(const float2*)&arow0[col];
                float2 a1 = *(const float2*)&arow1[col];
                float2 a2 = *(const float2*)&arow0[col + 8];
                float2 a3 = *(const float2*)&arow1[col + 8];
                float hx, hy;
                hx = bf16_hi_f(a0.x); hy = bf16_hi_f(a0.y);
                ahi[0] = pack_bf2(hx, hy); alo[0] = pack_bf2(a0.x - hx, a0.y - hy);
                hx = bf16_hi_f(a1.x); hy = bf16_hi_f(a1.y);
                ahi[1] = pack_bf2(hx, hy); alo[1] = pack_bf2(a1.x - hx, a1.y - hy);
                hx = bf16_hi_f(a2.x); hy = bf16_hi_f(a2.y);
                ahi[2] = pack_bf2(hx, hy); alo[2] = pack_bf2(a2.x - hx, a2.y - hy);
                hx = bf16_hi_f(a3.x); hy = bf16_hi_f(a3.y);
                ahi[3] = pack_bf2(hx, hy); alo[3] = pack_bf2(a3.x - hx, a3.y - hy);
            }
            #pragma unroll
            for (int nt = 0; nt < 8; nt++) {
                int base = (kc * 8 + tg) * 72 + nt * 8 + g;
                unsigned b0h = Whi[base], b1h = Whi[base + 4 * 72];
                unsigned b0l = Wlo[base], b1l = Wlo[base + 4 * 72];
                MMA_BF16(C[nt], ahi, b0h, b1h);
                MMA_BF16(C[nt], ahi, b0l, b1l);
                MMA_BF16(C[nt], alo, b0h, b1h);
            }
        }
    }

    #pragma unroll
    for (int nt = 0; nt < 8; nt++) {
        float2 bv = *(const float2*)&bo[noff + nt * 8 + 2 * tg];
        int m0 = mrow0 + g;
        float2 r0, r1;
        r0.x = C[nt][0] + bv.x; r0.y = C[nt][1] + bv.y;
        r1.x = C[nt][2] + bv.x; r1.y = C[nt][3] + bv.y;
        *(float2*)&out[(size_t)m0 * 256 + noff + nt * 8 + 2 * tg] = r0;
        *(float2*)&out[(size_t)(m0 + 8) * 256 + noff + nt * 8 + 2 * tg] = r1;
    }
}

// ---------------------------------------------------------------------------
extern "C" void kernel_launch(void* const* d_in, const int* in_sizes, int n_in,
                              void* d_out, int out_size)
{
    const float* X  = (const float*)d_in[0];
    const float* em = (const float*)d_in[1];
    const float* dw = (const float*)d_in[2];
    const float* Wq = (const float*)d_in[3];
    const float* Wk = (const float*)d_in[4];
    const float* Wv = (const float*)d_in[5];
    const float* Wo = (const float*)d_in[6];
    const float* bo = (const float*)d_in[7];
    float* out = (float*)d_out;

    qkv_kernel  <<<dim3(64, 8, 3), 256>>>(X, Wq, Wk, Wv);
    attn_kernel <<<dim3(8, 8, 8), 256>>>(em, dw);
    oproj_kernel<<<dim3(64, 4, 1), 256>>>(Wo, bo, out);
}

// round 7
// speedup vs baseline: 2.2892x; 1.0160x over previous
#include <cuda_runtime.h>
#include <cuda_bf16.h>
#include <math.h>

// ---------------------------------------------------------------------------
// CrystalGraphAttention  (B=8, N=1024, D=256, H=8, dk=dv=64)
//
//   q,k,v = X @ W{q,k,v}   (kernel 1, bf16 m16n8k16 3-term, pipelined)
//   flash attention        (kernel 2, bf16 m16n8k16 3-term, 2 blocks/SM)
//   out = ctx @ Wo + bo    (kernel 3, bf16 m16n8k16 3-term, pipelined)
// ---------------------------------------------------------------------------

#define NEGBIG (-1.0e9f)

static __device__ float g_q [8 * 8 * 1024 * 64];    // [B,H,N,64]
static __device__ float g_k [8 * 8 * 1024 * 64];
static __device__ float g_v [8 * 8 * 1024 * 64];
static __device__ float g_ctx[8 * 1024 * 512];      // [B*N, H*64]

// ---------------------------------------------------------------------------
// bf16 mma helpers
// ---------------------------------------------------------------------------
#define MMA_BF16(c, a, b0, b1)                                              \
    asm volatile(                                                           \
        "mma.sync.aligned.m16n8k16.row.col.f32.bf16.bf16.f32 "              \
        "{%0,%1,%2,%3}, {%4,%5,%6,%7}, {%8,%9}, {%0,%1,%2,%3};"             \
        : "+f"((c)[0]), "+f"((c)[1]), "+f"((c)[2]), "+f"((c)[3])            \
        : "r"((a)[0]), "r"((a)[1]), "r"((a)[2]), "r"((a)[3]),               \
          "r"(b0), "r"(b1))

__device__ __forceinline__ unsigned pack_bf2(float x, float y)
{
    unsigned r;
    asm("cvt.rn.bf16x2.f32 %0, %1, %2;" : "=r"(r) : "f"(y), "f"(x));
    return r;
}

__device__ __forceinline__ float bf16_hi_f(float x)
{
    return __bfloat162float(__float2bfloat16(x));
}

// ---------------------------------------------------------------------------
// Kernel 1: QKV projection, bf16 3-term, register-pipelined W staging.
// grid = (64 mtiles, 8 heads, 3 weights), block = 256 (8 warps).
// ---------------------------------------------------------------------------
__global__ __launch_bounds__(256, 2) void qkv_kernel(
    const float* __restrict__ X,
    const float* __restrict__ Wq,
    const float* __restrict__ Wk,
    const float* __restrict__ Wv)
{
    __shared__ __align__(16) unsigned Whi[16 * 72];
    __shared__ __align__(16) unsigned Wlo[16 * 72];

    const int tid  = threadIdx.x;
    const int wid  = tid >> 5;
    const int lane = tid & 31;
    const int g    = lane >> 2;
    const int tg   = lane & 3;
    const int mt = blockIdx.x, h = blockIdx.y, w = blockIdx.z;
    const float* W = (w == 0) ? Wq : (w == 1) ? Wk : Wv;
    float* Out     = (w == 0) ? g_q : (w == 1) ? g_k : g_v;

    const int mrow0 = mt * 128 + wid * 16;
    const float* arow0 = &X[(size_t)(mrow0 + g) * 256];
    const float* arow1 = arow0 + 8 * 256;

    const int kp = tid >> 4;              // 0..15 (k-pair for staging)
    const int n4 = (tid & 15) * 4;        // n base for staging

    // ---- preload first W chunk into registers ----
    const float* wptr = &W[(size_t)(2 * kp) * 512 + h * 64 + n4];
    float4 w0 = *(const float4*)wptr;
    float4 w1 = *(const float4*)(wptr + 512);

    float C[8][4];
    #pragma unroll
    for (int nt = 0; nt < 8; nt++)
        #pragma unroll
        for (int j = 0; j < 4; j++) C[nt][j] = 0.f;

    for (int k0 = 0; k0 < 256; k0 += 32) {
        // ---- issue A loads for this chunk early (overlap staging) ----
        float2 a[8];
        #pragma unroll
        for (int kc = 0; kc < 2; kc++) {
            int col = k0 + kc * 16 + 2 * tg;
            a[kc * 4 + 0] = *(const float2*)&arow0[col];
            a[kc * 4 + 1] = *(const float2*)&arow1[col];
            a[kc * 4 + 2] = *(const float2*)&arow0[col + 8];
            a[kc * 4 + 3] = *(const float2*)&arow1[col + 8];
        }

        __syncthreads();
        // ---- stage W chunk from registers ----
        {
            float h0x = bf16_hi_f(w0.x), h1x = bf16_hi_f(w1.x);
            float h0y = bf16_hi_f(w0.y), h1y = bf16_hi_f(w1.y);
            float h0z = bf16_hi_f(w0.z), h1z = bf16_hi_f(w1.z);
            float h0w = bf16_hi_f(w0.w), h1w = bf16_hi_f(w1.w);
            uint4 hi4, lo4;
            hi4.x = pack_bf2(h0x, h1x);
            hi4.y = pack_bf2(h0y, h1y);
            hi4.z = pack_bf2(h0z, h1z);
            hi4.w = pack_bf2(h0w, h1w);
            lo4.x = pack_bf2(w0.x - h0x, w1.x - h1x);
            lo4.y = pack_bf2(w0.y - h0y, w1.y - h1y);
            lo4.z = pack_bf2(w0.z - h0z, w1.z - h1z);
            lo4.w = pack_bf2(w0.w - h0w, w1.w - h1w);
            *(uint4*)&Whi[kp * 72 + n4] = hi4;
            *(uint4*)&Wlo[kp * 72 + n4] = lo4;
        }
        __syncthreads();

        // ---- prefetch next W chunk (overlaps MMAs below) ----
        if (k0 + 32 < 256) {
            wptr += 32 * 512;
            w0 = *(const float4*)wptr;
            w1 = *(const float4*)(wptr + 512);
        }

        #pragma unroll
        for (int kc = 0; kc < 2; kc++) {
            unsigned ahi[4], alo[4];
            #pragma unroll
            for (int j = 0; j < 4; j++) {
                float2 av = a[kc * 4 + j];
                float hx = bf16_hi_f(av.x), hy = bf16_hi_f(av.y);
                ahi[j] = pack_bf2(hx, hy);
                alo[j] = pack_bf2(av.x - hx, av.y - hy);
            }
            #pragma unroll
            for (int nt = 0; nt < 8; nt++) {
                int base = (kc * 8 + tg) * 72 + nt * 8 + g;
                unsigned b0h = Whi[base], b1h = Whi[base + 4 * 72];
                unsigned b0l = Wlo[base], b1l = Wlo[base + 4 * 72];
                MMA_BF16(C[nt], ahi, b0h, b1h);
                MMA_BF16(C[nt], ahi, b0l, b1l);
                MMA_BF16(C[nt], alo, b0h, b1h);
            }
        }
    }

    // ---- write to [B,H,N,64] ----
    #pragma unroll
    for (int nt = 0; nt < 8; nt++) {
        int m0 = mrow0 + g;
        int m1 = m0 + 8;
        int b0i = m0 >> 10, s0 = m0 & 1023;
        int b1i = m1 >> 10, s1 = m1 & 1023;
        float2 r0, r1;
        r0.x = C[nt][0]; r0.y = C[nt][1];
        r1.x = C[nt][2]; r1.y = C[nt][3];
        *(float2*)&Out[(size_t)((b0i * 8 + h) * 1024 + s0) * 64 + nt * 8 + 2 * tg] = r0;
        *(float2*)&Out[(size_t)((b1i * 8 + h) * 1024 + s1) * 64 + nt * 8 + 2 * tg] = r1;
    }
}

// ---------------------------------------------------------------------------
// Kernel 2: flash attention, bf16 3-term, 2 blocks/SM.
// grid = (8 qtiles, 8 heads, 8 batches), block = 256 (8 warps).
// Mask/dw loaded inline in the modulation loop (unrolled -> batched LDGs);
// latency covered by the co-resident block.
// ---------------------------------------------------------------------------
__global__ __launch_bounds__(256, 2) void attn_kernel(
    const float* __restrict__ em,     // [B,1,N,N]
    const float* __restrict__ dw)     // [B,N]
{
    __shared__ __align__(16) unsigned KsHi[64 * 36];   // [key][dpair]
    __shared__ __align__(16) unsigned KsLo[64 * 36];
    __shared__ __align__(16) unsigned VtHi[64 * 40];   // [d][keypair]
    __shared__ __align__(16) unsigned VtLo[64 * 40];

    const int tid  = threadIdx.x;
    const int wid  = tid >> 5;
    const int lane = tid & 31;
    const int g    = lane >> 2;
    const int tg   = lane & 3;
    const int qt = blockIdx.x, h = blockIdx.y, b = blockIdx.z;
    const int qrow0 = qt * 128 + wid * 16;

    const float* qb = &g_q[(size_t)((b * 8 + h) * 1024 + qrow0) * 64];
    const float* kb = &g_k[(size_t)(b * 8 + h) * 1024 * 64];
    const float* vb = &g_v[(size_t)(b * 8 + h) * 1024 * 64];
    const float* emb = em + (size_t)b * 1024 * 1024;
    const float* dwb = dw + b * 1024;

    // ---- Q fragments (scaled by 1/8), packed bf16x2 hi/lo, resident ----
    unsigned qhi[4][4], qlo[4][4];
    #pragma unroll
    for (int kc = 0; kc < 4; kc++) {
        #pragma unroll
        for (int j = 0; j < 4; j++) {
            int row = (j & 1) ? g + 8 : g;
            int col = kc * 16 + 2 * tg + ((j >> 1) ? 8 : 0);
            float2 qv = *(const float2*)&qb[(size_t)row * 64 + col];
            qv.x *= 0.125f; qv.y *= 0.125f;
            float hx = bf16_hi_f(qv.x), hy = bf16_hi_f(qv.y);
            qhi[kc][j] = pack_bf2(hx, hy);
            qlo[kc][j] = pack_bf2(qv.x - hx, qv.y - hy);
        }
    }

    float O[8][4];
    #pragma unroll
    for (int nt = 0; nt < 8; nt++)
        #pragma unroll
        for (int j = 0; j < 4; j++) O[nt][j] = 0.f;
    float mi0 = -1e30f, mi1 = -1e30f, li0 = 0.f, li1 = 0.f;

    // staging thread maps
    const int kr = tid >> 4;            // K: key row base (0..15)
    const int kc4 = (tid & 15) * 4;     // K: d base
    const int vkp = tid & 31;           // V: keypair (0..31)
    const int vd0 = (tid >> 5) * 8;     // V: d group base

    for (int kt = 0; kt < 16; kt++) {
        __syncthreads();
        // ---- stage K (hi/lo, [key][dpair]) ----
        {
            int r = kr;
            #pragma unroll
            for (int t = 0; t < 4; t++, r += 16) {
                float4 kv = *(const float4*)&kb[(size_t)(kt * 64 + r) * 64 + kc4];
                float h0 = bf16_hi_f(kv.x), h1 = bf16_hi_f(kv.y);
                float h2 = bf16_hi_f(kv.z), h3 = bf16_hi_f(kv.w);
                uint2 hp, lp;
                hp.x = pack_bf2(h0, h1);          hp.y = pack_bf2(h2, h3);
                lp.x = pack_bf2(kv.x - h0, kv.y - h1);
                lp.y = pack_bf2(kv.z - h2, kv.w - h3);
                *(uint2*)&KsHi[r * 36 + kc4 / 2] = hp;
                *(uint2*)&KsLo[r * 36 + kc4 / 2] = lp;
            }
        }
        // ---- stage V transposed (hi/lo, [d][keypair]) ----
        {
            const float* vr0 = &vb[(size_t)(kt * 64 + 2 * vkp) * 64 + vd0];
            const float* vr1 = vr0 + 64;
            float e0[8], e1[8];
            float4 t0 = *(const float4*)&vr0[0];
            float4 t1 = *(const float4*)&vr0[4];
            float4 u0 = *(const float4*)&vr1[0];
            float4 u1 = *(const float4*)&vr1[4];
            e0[0]=t0.x; e0[1]=t0.y; e0[2]=t0.z; e0[3]=t0.w;
            e0[4]=t1.x; e0[5]=t1.y; e0[6]=t1.z; e0[7]=t1.w;
            e1[0]=u0.x; e1[1]=u0.y; e1[2]=u0.z; e1[3]=u0.w;
            e1[4]=u1.x; e1[5]=u1.y; e1[6]=u1.z; e1[7]=u1.w;
            #pragma unroll
            for (int i = 0; i < 8; i++) {
                float h0 = bf16_hi_f(e0[i]), h1 = bf16_hi_f(e1[i]);
                VtHi[(vd0 + i) * 40 + vkp] = pack_bf2(h0, h1);
                VtLo[(vd0 + i) * 40 + vkp] = pack_bf2(e0[i] - h0, e1[i] - h1);
            }
        }
        __syncthreads();

        // ---- S = (Q/8) K^T  (3-term bf16) ----
        float S[8][4];
        #pragma unroll
        for (int nt = 0; nt < 8; nt++) {
            S[nt][0] = S[nt][1] = S[nt][2] = S[nt][3] = 0.f;
            #pragma unroll
            for (int kc = 0; kc < 4; kc++) {
                int base = (nt * 8 + g) * 36 + kc * 8 + tg;
                unsigned b0h = KsHi[base], b1h = KsHi[base + 4];
                unsigned b0l = KsLo[base], b1l = KsLo[base + 4];
                MMA_BF16(S[nt], qhi[kc], b0h, b1h);
                MMA_BF16(S[nt], qhi[kc], b0l, b1l);
                MMA_BF16(S[nt], qlo[kc], b0h, b1h);
            }
        }

        // ---- mask + distance modulation + online softmax (inline loads) ----
        const float* er0 = emb + (size_t)(qrow0 + g) * 1024 + kt * 64;
        const float* er1 = er0 + (size_t)8 * 1024;
        const float* dr  = dwb + kt * 64;
        float rm0 = -1e30f, rm1 = -1e30f;
        #pragma unroll
        for (int nt = 0; nt < 8; nt++) {
            float2 m0v = *(const float2*)&er0[nt * 8 + 2 * tg];
            float2 m1v = *(const float2*)&er1[nt * 8 + 2 * tg];
            float2 dv  = *(const float2*)&dr [nt * 8 + 2 * tg];
            float l0 = (S[nt][0] + (1.f - m0v.x) * NEGBIG) * dv.x;
            float l1 = (S[nt][1] + (1.f - m0v.y) * NEGBIG) * dv.y;
            float l2 = (S[nt][2] + (1.f - m1v.x) * NEGBIG) * dv.x;
            float l3 = (S[nt][3] + (1.f - m1v.y) * NEGBIG) * dv.y;
            S[nt][0] = l0; S[nt][1] = l1; S[nt][2] = l2; S[nt][3] = l3;
            rm0 = fmaxf(rm0, fmaxf(l0, l1));
            rm1 = fmaxf(rm1, fmaxf(l2, l3));
        }
        #pragma unroll
        for (int off = 1; off <= 2; off <<= 1) {
            rm0 = fmaxf(rm0, __shfl_xor_sync(0xffffffffu, rm0, off));
            rm1 = fmaxf(rm1, __shfl_xor_sync(0xffffffffu, rm1, off));
        }
        float nm0 = fmaxf(mi0, rm0), nm1 = fmaxf(mi1, rm1);
        float corr0 = __expf(mi0 - nm0), corr1 = __expf(mi1 - nm1);

        float rs0 = 0.f, rs1 = 0.f;
        #pragma unroll
        for (int nt = 0; nt < 8; nt++) {
            float p0 = __expf(S[nt][0] - nm0);
            float p1 = __expf(S[nt][1] - nm0);
            float p2 = __expf(S[nt][2] - nm1);
            float p3 = __expf(S[nt][3] - nm1);
            S[nt][0] = p0; S[nt][1] = p1; S[nt][2] = p2; S[nt][3] = p3;
            rs0 += p0 + p1; rs1 += p2 + p3;
        }
        #pragma unroll
        for (int off = 1; off <= 2; off <<= 1) {
            rs0 += __shfl_xor_sync(0xffffffffu, rs0, off);
            rs1 += __shfl_xor_sync(0xffffffffu, rs1, off);
        }
        li0 = li0 * corr0 + rs0;  mi0 = nm0;
        li1 = li1 * corr1 + rs1;  mi1 = nm1;
        #pragma unroll
        for (int nt = 0; nt < 8; nt++) {
            O[nt][0] *= corr0; O[nt][1] *= corr0;
            O[nt][2] *= corr1; O[nt][3] *= corr1;
        }

        // ---- O += P V  (3-term bf16; P A-frags come straight from S) ----
        #pragma unroll
        for (int kc = 0; kc < 4; kc++) {
            unsigned pa_h[4], pa_l[4];
            #pragma unroll
            for (int j = 0; j < 4; j++) {
                float x = S[2 * kc + (j >> 1)][(j & 1) ? 2 : 0];
                float y = S[2 * kc + (j >> 1)][(j & 1) ? 3 : 1];
                float hx = bf16_hi_f(x), hy = bf16_hi_f(y);
                pa_h[j] = pack_bf2(hx, hy);
                pa_l[j] = pack_bf2(x - hx, y - hy);
            }
            #pragma unroll
            for (int nt = 0; nt < 8; nt++) {
                int base = (nt * 8 + g) * 40 + kc * 8 + tg;
                unsigned b0h = VtHi[base], b1h = VtHi[base + 4];
                unsigned b0l = VtLo[base], b1l = VtLo[base + 4];
                MMA_BF16(O[nt], pa_h, b0h, b1h);
                MMA_BF16(O[nt], pa_h, b0l, b1l);
                MMA_BF16(O[nt], pa_l, b0h, b1h);
            }
        }
    }

    // ---- epilogue: normalize and write ctx ----
    float inv0 = 1.f / li0, inv1 = 1.f / li1;
    #pragma unroll
    for (int nt = 0; nt < 8; nt++) {
        float2 r0, r1;
        r0.x = O[nt][0] * inv0; r0.y = O[nt][1] * inv0;
        r1.x = O[nt][2] * inv1; r1.y = O[nt][3] * inv1;
        *(float2*)&g_ctx[(size_t)(b * 1024 + qrow0 + g) * 512
                         + h * 64 + nt * 8 + 2 * tg] = r0;
        *(float2*)&g_ctx[(size_t)(b * 1024 + qrow0 + g + 8) * 512
                         + h * 64 + nt * 8 + 2 * tg] = r1;
    }
}

// ---------------------------------------------------------------------------
// Kernel 3: output projection, bf16 3-term, register-pipelined W staging.
// grid = (64 mtiles, 4 ntiles), block = 256.  K=512.
// ---------------------------------------------------------------------------
__global__ __launch_bounds__(256, 2) void oproj_kernel(
    const float* __restrict__ Wo,
    const float* __restrict__ bo,
    float* __restrict__ out)
{
    __shared__ __align__(16) unsigned Whi[16 * 72];
    __shared__ __align__(16) unsigned Wlo[16 * 72];

    const int tid  = threadIdx.x;
    const int wid  = tid >> 5;
    const int lane = tid & 31;
    const int g    = lane >> 2;
    const int tg   = lane & 3;
    const int mt = blockIdx.x;
    const int ntile = blockIdx.y;
    const int noff = ntile * 64;

    const int mrow0 = mt * 128 + wid * 16;
    const float* arow0 = &g_ctx[(size_t)(mrow0 + g) * 512];
    const float* arow1 = arow0 + 8 * 512;

    const int kp = tid >> 4;
    const int n4 = (tid & 15) * 4;

    const float* wptr = &Wo[(size_t)(2 * kp) * 256 + noff + n4];
    float4 w0 = *(const float4*)wptr;
    float4 w1 = *(const float4*)(wptr + 256);

    float C[8][4];
    #pragma unroll
    for (int nt = 0; nt < 8; nt++)
        #pragma unroll
        for (int j = 0; j < 4; j++) C[nt][j] = 0.f;

    for (int k0 = 0; k0 < 512; k0 += 32) {
        float2 a[8];
        #pragma unroll
        for (int kc = 0; kc < 2; kc++) {
            int col = k0 + kc * 16 + 2 * tg;
            a[kc * 4 + 0] = *(const float2*)&arow0[col];
            a[kc * 4 + 1] = *(const float2*)&arow1[col];
            a[kc * 4 + 2] = *(const float2*)&arow0[col + 8];
            a[kc * 4 + 3] = *(const float2*)&arow1[col + 8];
        }

        __syncthreads();
        {
            float h0x = bf16_hi_f(w0.x), h1x = bf16_hi_f(w1.x);
            float h0y = bf16_hi_f(w0.y), h1y = bf16_hi_f(w1.y);
            float h0z = bf16_hi_f(w0.z), h1z = bf16_hi_f(w1.z);
            float h0w = bf16_hi_f(w0.w), h1w = bf16_hi_f(w1.w);
            uint4 hi4, lo4;
            hi4.x = pack_bf2(h0x, h1x);
            hi4.y = pack_bf2(h0y, h1y);
            hi4.z = pack_bf2(h0z, h1z);
            hi4.w = pack_bf2(h0w, h1w);
            lo4.x = pack_bf2(w0.x - h0x, w1.x - h1x);
            lo4.y = pack_bf2(w0.y - h0y, w1.y - h1y);
            lo4.z = pack_bf2(w0.z - h0z, w1.z - h1z);
            lo4.w = pack_bf2(w0.w - h0w, w1.w - h1w);
            *(uint4*)&Whi[kp * 72 + n4] = hi4;
            *(uint4*)&Wlo[kp * 72 + n4] = lo4;
        }
        __syncthreads();

        if (k0 + 32 < 512) {
            wptr += 32 * 256;
            w0 = *(const float4*)wptr;
            w1 = *(const float4*)(wptr + 256);
        }

        #pragma unroll
        for (int kc = 0; kc < 2; kc++) {
            unsigned ahi[4], alo[4];
            #pragma unroll
            for (int j = 0; j < 4; j++) {
                float2 av = a[kc * 4 + j];
                float hx = bf16_hi_f(av.x), hy = bf16_hi_f(av.y);
                ahi[j] = pack_bf2(hx, hy);
                alo[j] = pack_bf2(av.x - hx, av.y - hy);
            }
            #pragma unroll
            for (int nt = 0; nt < 8; nt++) {
                int base = (kc * 8 + tg) * 72 + nt * 8 + g;
                unsigned b0h = Whi[base], b1h = Whi[base + 4 * 72];
                unsigned b0l = Wlo[base], b1l = Wlo[base + 4 * 72];
                MMA_BF16(C[nt], ahi, b0h, b1h);
                MMA_BF16(C[nt], ahi, b0l, b1l);
                MMA_BF16(C[nt], alo, b0h, b1h);
            }
        }
    }

    #pragma unroll
    for (int nt = 0; nt < 8; nt++) {
        float2 bv = *(const float2*)&bo[noff + nt * 8 + 2 * tg];
        int m0 = mrow0 + g;
        float2 r0, r1;
        r0.x = C[nt][0] + bv.x; r0.y = C[nt][1] + bv.y;
        r1.x = C[nt][2] + bv.x; r1.y = C[nt][3] + bv.y;
        *(float2*)&out[(size_t)m0 * 256 + noff + nt * 8 + 2 * tg] = r0;
        *(float2*)&out[(size_t)(m0 + 8) * 256 + noff + nt * 8 + 2 * tg] = r1;
    }
}

// ---------------------------------------------------------------------------
extern "C" void kernel_launch(void* const* d_in, const int* in_sizes, int n_in,
                              void* d_out, int out_size)
{
    const float* X  = (const float*)d_in[0];
    const float* em = (const float*)d_in[1];
    const float* dw = (const float*)d_in[2];
    const float* Wq = (const float*)d_in[3];
    const float* Wk = (const float*)d_in[4];
    const float* Wv = (const float*)d_in[5];
    const float* Wo = (const float*)d_in[6];
    const float* bo = (const float*)d_in[7];
    float* out = (float*)d_out;

    qkv_kernel  <<<dim3(64, 8, 3), 256>>>(X, Wq, Wk, Wv);
    attn_kernel <<<dim3(8, 8, 8), 256>>>(em, dw);
    oproj_kernel<<<dim3(64, 4, 1), 256>>>(Wo, bo, out);
}